// round 16
// baseline (speedup 1.0000x reference)
#include <cuda_runtime.h>
#include <cstdint>

#define BATCH 32
#define L_ 512
#define T_ 64
#define NCHUNK 9
#define CSTEPS 57
#define EPITCH 66

__device__ float g_a[BATCH][NCHUNK][T_];
__device__ float g_bv[BATCH][NCHUNK][T_];
__device__ int   g_eb[BATCH][NCHUNK];
__device__ int   g_cnt[BATCH];   // zero-init; reset by combiner

typedef unsigned long long u64;
__device__ __forceinline__ u64 pk(float lo, float hi) {
    u64 r; asm("mov.b64 %0,{%1,%2};" : "=l"(r) : "f"(lo), "f"(hi)); return r;
}
__device__ __forceinline__ void upk(u64 v, float& lo, float& hi) {
    asm("mov.b64 {%0,%1},%2;" : "=f"(lo), "=f"(hi) : "l"(v));
}
#define FMA2(acc, a, b) asm("fma.rn.f32x2 %0,%1,%2,%0;" : "+l"(acc) : "l"(a), "l"(b))
#define ADD2(d, a, b)   asm("add.rn.f32x2 %0,%1,%2;"    : "=l"(d)   : "l"(a), "l"(b))
#define BARX(id) asm volatile("bar.sync %0, 128;" :: "r"(id) : "memory")
__device__ __forceinline__ int expo(float x) {
    return ((__float_as_int(x) >> 23) & 255) - 127;
}

// ===========================================================================
// CTA = (batch b, chunk c), 256 threads, 57 steps.
//  Warps 0-3 (fwd, bar 1): lane pair (2 lanes) per output column j; each lane
//    holds HALF of E[:,j] (16 u64 = 32 regs). Per step: 8x LDS.128 of its
//    u-half + 16 FMA2 + shfl_xor(1) + g*2^-e scale + STS (h==0).
//  Warps 4-7 (bwd, bar 2): lane pair per row i, half of E[i,:]; per step
//    h==0 stores w_i = g*b*2^-e, bar, everyone loads w-half, 16 FMA2, shfl.
//  Exact 2^e renorm; masked/OOB steps skipped (exact identity).
//  Phase 2: last-arriver CTA of each batch combines:
//    logZ = sum_c log(b_c.a_{c-1}) - sum_{c<8} log(1^T a_c) + ln2*sum EB
// ===========================================================================
__global__ void __launch_bounds__(256, 2) crf_rank1_fused(
    const float* __restrict__ logits,
    const int* __restrict__ mask,
    const float* __restrict__ trans,
    float* __restrict__ out)
{
    __shared__ __align__(16) float Ex[T_ * EPITCH];
    __shared__ __align__(16) float ubuf[2][T_];
    __shared__ __align__(16) float wbuf[2][T_];
    __shared__ int msk_s[CSTEPS];
    __shared__ int old_s;
    __shared__ float dots_s[NCHUNK], gams_s[NCHUNK];
    __shared__ int eb_s[NCHUNK];

    const int b = blockIdx.x / NCHUNK, c = blockIdx.x % NCHUNK;
    const int tid = threadIdx.x;
    const int t0 = 1 + CSTEPS * c;

    for (int i = tid; i < T_ * T_; i += 256)
        Ex[(i >> 6) * EPITCH + (i & 63)] = __expf(trans[i]);
    if (tid < CSTEPS) {
        int t = t0 + tid;
        msk_s[tid] = (t < L_) ? mask[(size_t)b * L_ + t] : 0;
    }
    if (tid < T_) ubuf[0][tid] = 1.0f;
    __syncthreads();

    if (tid < 128) {
        // ---------------- forward: lane pair per column j ----------------
        const int j = tid >> 1, h = tid & 1;
        const float* lgc = logits + (size_t)b * L_ * T_ + j;
        u64 F[16];
        #pragma unroll
        for (int k = 0; k < 16; k++)
            F[k] = pk(Ex[(32 * h + 2 * k) * EPITCH + j],
                      Ex[(32 * h + 2 * k + 1) * EPITCH + j]);
        float gA_ = lgc[(size_t)t0 * T_];
        float gB_ = lgc[(size_t)(t0 + 1) * T_];
        float ulast = 1.0f;
        int p = 0;
        #pragma unroll 1
        for (int i = 0; i < CSTEPS; i++) {
            float gp = gA_; gA_ = gB_;
            int t2 = t0 + i + 2;
            if (t2 < L_) gB_ = lgc[(size_t)t2 * T_];
            if (msk_s[i]) {
                float u0v = ubuf[p][0];                 // broadcast LDS
                float sc = __int_as_float((127 - expo(u0v)) << 23);
                const ulonglong2* u2 = (const ulonglong2*)(ubuf[p] + 32 * h);
                u64 a0 = 0, a1 = 0;
                #pragma unroll
                for (int k4 = 0; k4 < 8; k4++) {
                    ulonglong2 q = u2[k4];
                    FMA2(a0, q.x, F[2 * k4]);
                    FMA2(a1, q.y, F[2 * k4 + 1]);
                }
                u64 s0; ADD2(s0, a0, a1);
                float lo, hi; upk(s0, lo, hi);
                float part = lo + hi;
                part += __shfl_xor_sync(0xffffffffu, part, 1);
                ulast = part * __expf(gp) * sc;
                if (h == 0) ubuf[p ^ 1][j] = ulast;
                p ^= 1;
            }
            BARX(1);
        }
        if (h == 0) g_a[b][c][j] = ulast;
    } else {
        // ---------------- backward: lane pair per row i ------------------
        const int bt = tid - 128;
        const int irow = bt >> 1, h = bt & 1;
        const float* lgc = logits + (size_t)b * L_ * T_ + irow;
        u64 Br[16];
        #pragma unroll
        for (int k = 0; k < 16; k++)
            Br[k] = *(const u64*)&Ex[irow * EPITCH + 32 * h + 2 * k];
        const int thi = t0 + CSTEPS - 1;
        float gA_ = (thi < L_) ? lgc[(size_t)thi * T_] : 0.0f;
        float gB_ = (thi - 1 < L_) ? lgc[(size_t)(thi - 1) * T_] : 0.0f;
        float bl = 1.0f;
        int ecarry = 0, keb = 0, q = 0;
        #pragma unroll 1
        for (int i = CSTEPS - 1; i >= 0; i--) {
            float gp = gA_; gA_ = gB_;
            if (i >= 2) gB_ = lgc[(size_t)(t0 + i - 2) * T_];
            if (msk_s[i]) {
                float sc = __int_as_float((127 - ecarry) << 23);
                keb += ecarry;
                if (h == 0) wbuf[q][irow] = __expf(gp) * bl * sc;
            }
            BARX(2);
            if (msk_s[i]) {
                float w0v = wbuf[q][0];                 // broadcast LDS
                ecarry = expo(w0v);
                const ulonglong2* w2 = (const ulonglong2*)(wbuf[q] + 32 * h);
                u64 a0 = 0, a1 = 0;
                #pragma unroll
                for (int k4 = 0; k4 < 8; k4++) {
                    ulonglong2 qq = w2[k4];
                    FMA2(a0, qq.x, Br[2 * k4]);
                    FMA2(a1, qq.y, Br[2 * k4 + 1]);
                }
                u64 s0; ADD2(s0, a0, a1);
                float lo, hi; upk(s0, lo, hi);
                float part = lo + hi;
                part += __shfl_xor_sync(0xffffffffu, part, 1);
                bl = part;
                q ^= 1;
            }
        }
        if (h == 0) g_bv[b][c][irow] = bl;
        if (bt == 0) g_eb[b][c] = keb;
    }

    // ---------------- Phase 2: last-arriver combine ----------------
    __threadfence();
    __syncthreads();
    if (tid == 0) old_s = atomicAdd(&g_cnt[b], 1);
    __syncthreads();
    if (old_s != NCHUNK - 1) return;
    __threadfence();   // acquire

    {
        const int cc = tid >> 4, q16 = tid & 15;   // 16 groups x 16 lanes
        const int ccl = (cc < NCHUNK) ? cc : NCHUNK - 1;   // clamp, uniform shfl
        float4 pv;
        if (ccl == 0) {
            const float m0 = (mask[(size_t)b * L_] != 0) ? 1.0f : 0.0f;
            const float* lg0 = logits + (size_t)b * L_ * T_ + q16 * 4;
            pv = make_float4(__expf(lg0[0] * m0), __expf(lg0[1] * m0),
                             __expf(lg0[2] * m0), __expf(lg0[3] * m0));
        } else {
            pv = *(const float4*)&g_a[b][ccl - 1][q16 * 4];
        }
        float4 bb = *(const float4*)&g_bv[b][ccl][q16 * 4];
        float4 aa = *(const float4*)&g_a[b][ccl][q16 * 4];
        float dv = bb.x * pv.x + bb.y * pv.y + bb.z * pv.z + bb.w * pv.w;
        float ga = aa.x + aa.y + aa.z + aa.w;
        dv += __shfl_xor_sync(0xffffffffu, dv, 8);
        dv += __shfl_xor_sync(0xffffffffu, dv, 4);
        dv += __shfl_xor_sync(0xffffffffu, dv, 2);
        dv += __shfl_xor_sync(0xffffffffu, dv, 1);
        ga += __shfl_xor_sync(0xffffffffu, ga, 8);
        ga += __shfl_xor_sync(0xffffffffu, ga, 4);
        ga += __shfl_xor_sync(0xffffffffu, ga, 2);
        ga += __shfl_xor_sync(0xffffffffu, ga, 1);
        if (q16 == 0 && cc < NCHUNK) { dots_s[cc] = dv; gams_s[cc] = ga; }
        if (tid < NCHUNK) eb_s[tid] = g_eb[b][tid];
        __syncthreads();

        if (tid == 0) {
            float s = 0.0f; int ebs = 0;
            #pragma unroll
            for (int k = 0; k < NCHUNK; k++) { s += __logf(dots_s[k]); ebs += eb_s[k]; }
            #pragma unroll
            for (int k = 0; k < NCHUNK - 1; k++) s -= __logf(gams_s[k]);
            out[b] = s + 0.6931471805599453f * (float)ebs;
            g_cnt[b] = 0;   // reset for next replay
        }
    }
}

extern "C" void kernel_launch(void* const* d_in, const int* in_sizes, int n_in,
                              void* d_out, int out_size) {
    const float* logits = (const float*)d_in[0];  // (32,512,64) f32
    const int* mask     = (const int*)d_in[1];    // (32,512) bool -> int32
    const float* trans  = (const float*)d_in[2];  // (64,64) f32
    float* out          = (float*)d_out;          // (32,) f32
    (void)in_sizes; (void)n_in; (void)out_size;
    crf_rank1_fused<<<BATCH * NCHUNK, 256>>>(logits, mask, trans, out);
}